// round 11
// baseline (speedup 1.0000x reference)
#include <cuda_runtime.h>
#include <math.h>
#include <stdint.h>

#define TT   1024
#define BB   512
#define DIN  128
#define HH   512
#define DOUT 128

#define NG   16
#define NS   8
#define MB   32
#define JS   64
#define NTHR 512

// smem byte offsets
#define WPB   528            // w row pitch bytes (66 u64)
#define VPB   272            // v row pitch bytes (34 u64)
#define VBUF  17408          // one v buffer: 64 rows * 272
#define W_OFF 0              // 320*528 = 168960
#define V_OFF 168960         // 2*17408 = 34816
#define R_OFF 203776         // red: 3*32*66 floats = 25344
#define B_OFF 229120         // bias: 64*4
#define SMEM_TOTAL 229376

// k-pair-packed weights: W2[kq][j] = {w[j][2kq], w[j][2kq+1]}; kq<256 -> Wh, 256..319 -> Wx
__device__ unsigned long long g_W2[320 * 512];
// hidden state, k-pair-packed: g_h2[p][kq*512 + b] = {h[2kq][b], h[2kq+1][b]}
__device__ unsigned long long g_h2[2][256 * 512];
__device__ unsigned g_flag[NG][NS][32];

__global__ void prep_kernel(const float* __restrict__ Wh,
                            const float* __restrict__ Wx) {
    int i = blockIdx.x * blockDim.x + threadIdx.x;
    int stride = gridDim.x * blockDim.x;
    for (int idx = i; idx < 320 * 512; idx += stride) {
        int kq = idx >> 9;
        int j  = idx & 511;
        unsigned long long v;
        if (kq < 256)
            v = *reinterpret_cast<const unsigned long long*>(&Wh[j * HH + 2 * kq]);
        else
            v = *reinterpret_cast<const unsigned long long*>(&Wx[j * DIN + 2 * (kq - 256)]);
        g_W2[idx] = v;
    }
}

__global__ void zero_kernel() {
    int i = blockIdx.x * blockDim.x + threadIdx.x;
    int stride = gridDim.x * blockDim.x;
    unsigned long long* p = &g_h2[0][0];
    for (int k = i; k < 256 * 512; k += stride) p[k] = 0ull;
    unsigned* f = &g_flag[0][0][0];
    for (int k = i; k < NG * NS * 32; k += stride) f[k] = 0u;
}

__device__ __forceinline__ void lds_v2(uint64_t& a, uint64_t& b, uint32_t addr) {
    asm volatile("ld.shared.v2.u64 {%0,%1}, [%2];" : "=l"(a), "=l"(b) : "r"(addr));
}
#define FMA2(acc, w, h) \
    asm("fma.rn.f32x2 %0, %1, %2, %0;" : "+l"(acc) : "l"(w), "l"(h))

__device__ __forceinline__ float2 unpack2(uint64_t a) {
    float lo, hi;
    asm("mov.b64 {%0,%1}, %2;" : "=f"(lo), "=f"(hi) : "l"(a));
    return make_float2(lo, hi);
}

__global__ __launch_bounds__(NTHR, 1) void scan_kernel(
    const float* __restrict__ x,
    const float* __restrict__ bx,
    const float* __restrict__ bh,
    const float* __restrict__ Wy,
    const float* __restrict__ by,
    float* __restrict__ y)
{
    extern __shared__ char smem[];
    const uint32_t sb = (uint32_t)__cvta_generic_to_shared(smem);
    float* red    = reinterpret_cast<float*>(smem + R_OFF);
    float* bias_s = reinterpret_cast<float*>(smem + B_OFF);

    const int tid = threadIdx.x;
    const int g   = blockIdx.x >> 3;
    const int s   = blockIdx.x & 7;

    // compute decode: quarter z, 8 j-threads, 16 m-threads (2 m each)
    const int z  = tid >> 7;          // 0..3 (k-split quarter)
    const int jt = tid & 7;           // j pairs at cols {2jt+16p}, p=0..3
    const int mt = (tid >> 3) & 15;   // m = 2*mt + mm, mm=0..1

    // staging decode
    const int sr = tid >> 4;          // 0..31
    const int sc = tid & 15;          // 0..15 (16B units)
    // x staging decode
    const int xb  = tid & 31;
    const int xdc = tid >> 5;         // 0..15

    // ---- load weight slice into smem in CHUNK order (x rows first) ----
    for (int i = tid; i < 320 * 64; i += NTHR) {
        int wr = i >> 6, jl = i & 63;
        int w2row = (wr < 64) ? (256 + wr) : (wr - 64);
        reinterpret_cast<unsigned long long*>(smem + W_OFF)[wr * 66 + jl] =
            g_W2[(size_t)w2row * 512 + s * JS + jl];
    }
    if (tid < 64) bias_s[tid] = bx[s * JS + tid] + bh[s * JS + tid];

    const float* __restrict__ xrow = &x[(size_t)(g * MB + xb) * TT * DIN];

    float4 pre[2];
    // ---- prologue: stage x(t=0) into buf 0 ----
    #pragma unroll
    for (int it = 0; it < 2; ++it)
        pre[it] = __ldg(reinterpret_cast<const float4*>(xrow + (xdc + 16 * it) * 4));
    #pragma unroll
    for (int it = 0; it < 2; ++it) {
        int dq = xdc + 16 * it;
        char* b0 = smem + V_OFF + (2 * dq) * VPB + xb * 8;
        *reinterpret_cast<float2*>(b0)       = make_float2(pre[it].x, pre[it].y);
        *reinterpret_cast<float2*>(b0 + VPB) = make_float2(pre[it].z, pre[it].w);
    }
    __syncthreads();

    #define LDG_H(P, CH64)                                                       \
        do {                                                                     \
            const unsigned long long* hs = &g_h2[(P)][0];                        \
            _Pragma("unroll")                                                    \
            for (int it = 0; it < 2; ++it)                                       \
                pre[it] = __ldcg(reinterpret_cast<const float4*>(                \
                    hs + (size_t)((CH64) + sr + 32 * it) * 512 + g * MB + sc * 2)); \
        } while (0)

    #define STS_H(VB)                                                            \
        do {                                                                     \
            _Pragma("unroll")                                                    \
            for (int it = 0; it < 2; ++it)                                       \
                *reinterpret_cast<float4*>(smem + V_OFF + (VB) * VBUF +          \
                    (sr + 32 * it) * VPB + sc * 16) = pre[it];                   \
        } while (0)

    #define COMPUTE(C, VB)                                                       \
        do {                                                                     \
            uint32_t wa = sb + (uint32_t)(W_OFF + ((C) * 64 + z * 16) * WPB + jt * 16); \
            uint32_t va = sb + (uint32_t)(V_OFF + (VB) * VBUF + (z * 16) * VPB + mt * 16); \
            _Pragma("unroll")                                                    \
            for (int qq = 0; qq < 16; ++qq) {                                    \
                uint64_t w00,w01,w10,w11,w20,w21,w30,w31,h0,h1;                  \
                lds_v2(w00,w01, wa);                                             \
                lds_v2(w10,w11, wa + 128);                                       \
                lds_v2(w20,w21, wa + 256);                                       \
                lds_v2(w30,w31, wa + 384);                                       \
                lds_v2(h0,h1, va);                                               \
                FMA2(acc[ 0],w00,h0); FMA2(acc[ 1],w00,h1);                      \
                FMA2(acc[ 2],w01,h0); FMA2(acc[ 3],w01,h1);                      \
                FMA2(acc[ 4],w10,h0); FMA2(acc[ 5],w10,h1);                      \
                FMA2(acc[ 6],w11,h0); FMA2(acc[ 7],w11,h1);                      \
                FMA2(acc[ 8],w20,h0); FMA2(acc[ 9],w20,h1);                      \
                FMA2(acc[10],w21,h0); FMA2(acc[11],w21,h1);                      \
                FMA2(acc[12],w30,h0); FMA2(acc[13],w30,h1);                      \
                FMA2(acc[14],w31,h0); FMA2(acc[15],w31,h1);                      \
                wa += WPB; va += VPB;                                            \
            }                                                                    \
        } while (0)

    int p = 0;
    for (int t = 0; t < TT; ++t) {
        uint64_t acc[16];
        #pragma unroll
        for (int i = 0; i < 16; ++i) acc[i] = 0ull;

        LDG_H(p, 0);          // h chunk 0 in flight
        COMPUTE(0, p);        // x chunk (staged in buf p)
        STS_H(p ^ 1);
        __syncthreads();

        LDG_H(p, 64);
        COMPUTE(1, p ^ 1);
        STS_H(p);
        __syncthreads();

        LDG_H(p, 128);
        COMPUTE(2, p);
        STS_H(p ^ 1);
        __syncthreads();

        LDG_H(p, 192);
        COMPUTE(3, p ^ 1);
        STS_H(p);
        __syncthreads();

        // prefetch x(t+1), compute last chunk, stage x into buf p^1
        {
            const int tn = (t + 1 < TT) ? t + 1 : t;
            const float* xr = xrow + (size_t)tn * DIN;
            #pragma unroll
            for (int it = 0; it < 2; ++it)
                pre[it] = __ldg(reinterpret_cast<const float4*>(xr + (xdc + 16 * it) * 4));
        }
        COMPUTE(4, p);
        #pragma unroll
        for (int it = 0; it < 2; ++it) {
            int dq = xdc + 16 * it;
            char* b0 = smem + V_OFF + (p ^ 1) * VBUF + (2 * dq) * VPB + xb * 8;
            *reinterpret_cast<float2*>(b0)       = make_float2(pre[it].x, pre[it].y);
            *reinterpret_cast<float2*>(b0 + VPB) = make_float2(pre[it].z, pre[it].w);
        }

        // ---- R8-style centralized finalize ----
        if (z != 0) {
            #pragma unroll
            for (int pp = 0; pp < 4; ++pp)
                #pragma unroll
                for (int jj = 0; jj < 2; ++jj)
                    #pragma unroll
                    for (int mm = 0; mm < 2; ++mm) {
                        float2 v = unpack2(acc[pp * 4 + jj * 2 + mm]);
                        int j = 2 * jt + 16 * pp + jj;
                        int m = 2 * mt + mm;
                        red[((z - 1) * 32 + m) * 66 + j] = v.x + v.y;
                    }
        }
        __syncthreads();
        if (z == 0) {
            unsigned long long* hdst = &g_h2[p ^ 1][0];
            #pragma unroll
            for (int pp = 0; pp < 4; ++pp) {
                #pragma unroll
                for (int mm = 0; mm < 2; ++mm) {
                    float hv[2];
                    #pragma unroll
                    for (int jj = 0; jj < 2; ++jj) {
                        float2 v = unpack2(acc[pp * 4 + jj * 2 + mm]);
                        int j = 2 * jt + 16 * pp + jj;
                        int m = 2 * mt + mm;
                        float sum = v.x + v.y
                                  + red[(m) * 66 + j]
                                  + red[(32 + m) * 66 + j]
                                  + red[(64 + m) * 66 + j]
                                  + bias_s[j];
                        hv[jj] = tanhf(sum);
                    }
                    unsigned long long pk;
                    asm("mov.b64 %0, {%1,%2};" : "=l"(pk) : "f"(hv[0]), "f"(hv[1]));
                    size_t off = (size_t)(32 * s + jt + 8 * pp) * 512
                               + g * MB + 2 * mt + mm;
                    __stcg(&hdst[off], pk);
                }
            }
        }
        __syncthreads();
        if (tid == 0) {
            asm volatile("fence.acq_rel.gpu;" ::: "memory");
            asm volatile("st.release.gpu.global.u32 [%0], %1;"
                         :: "l"(&g_flag[g][s][0]), "r"((unsigned)(t + 1))
                         : "memory");
        }
        if (tid < NS) {
            const unsigned tgt = (unsigned)(t + 1);
            unsigned v;
            do {
                asm volatile("ld.acquire.gpu.global.u32 %0, [%1];"
                             : "=r"(v) : "l"(&g_flag[g][tid][0]));
            } while (v < tgt);
        }
        __syncthreads();
        p ^= 1;
    }

    // ---- epilogue: y = h_T @ Wy^T + by ; h_T packed in g_h2[0] ----
    const int o  = s * 16 + (tid & 15);
    const int me = tid >> 4;            // 0..31
    const unsigned long long* hfin = &g_h2[0][0];
    const unsigned long long* Wy2  = reinterpret_cast<const unsigned long long*>(Wy);
    uint64_t ya = 0ull;

    #pragma unroll
    for (int half = 0; half < 2; ++half) {
        __syncthreads();
        #pragma unroll
        for (int it = 0; it < 4; ++it) {
            int r = sr + 32 * it;       // 0..127
            float4 vv = __ldcg(reinterpret_cast<const float4*>(
                hfin + (size_t)(half * 128 + r) * 512 + g * MB + sc * 2));
            *reinterpret_cast<float4*>(smem + V_OFF + r * VPB + sc * 16) = vv;
        }
        __syncthreads();
        #pragma unroll 8
        for (int kq = 0; kq < 128; ++kq) {
            uint64_t h0 = *reinterpret_cast<uint64_t*>(
                smem + V_OFF + kq * VPB + me * 8);
            unsigned long long wv = __ldg(&Wy2[(size_t)o * 256 + half * 128 + kq]);
            FMA2(ya, wv, h0);
        }
    }
    {
        float2 a = unpack2(ya);
        y[(size_t)(g * MB + me) * DOUT + o] = by[o] + a.x + a.y;
    }
}

extern "C" void kernel_launch(void* const* d_in, const int* in_sizes, int n_in,
                              void* d_out, int out_size) {
    const float* x  = (const float*)d_in[0];
    const float* Wx = (const float*)d_in[1];
    const float* bx = (const float*)d_in[2];
    const float* Wh = (const float*)d_in[3];
    const float* bh = (const float*)d_in[4];
    const float* Wy = (const float*)d_in[5];
    const float* by = (const float*)d_in[6];
    float* y = (float*)d_out;

    cudaFuncSetAttribute(scan_kernel,
                         cudaFuncAttributeMaxDynamicSharedMemorySize, SMEM_TOTAL);

    prep_kernel<<<256, 256>>>(Wh, Wx);
    zero_kernel<<<256, 256>>>();
    scan_kernel<<<NG * NS, NTHR, SMEM_TOTAL>>>(x, bx, bh, Wy, by, y);
}

// round 13
// speedup vs baseline: 3.7939x; 3.7939x over previous
#include <cuda_runtime.h>
#include <cuda_fp16.h>
#include <math.h>
#include <stdint.h>

#define TT   1024
#define DIN  128
#define HH   512
#define DOUT 128
#define NG   16
#define NS   8
#define NTHR 256

// smem byte offsets
#define SM_W   0                        // 40 kt16 x 8 nt x 32 lane x 2 b32 = 81920 B
#define SM_A   81920                    // 2 bufs x [8 kt][2 mt][32][4 b32] = 16384 B
#define SM_BIAS (81920 + 16384)         // 64 floats
#define SMEM_TOTAL (SM_BIAS + 256)

// fragment-order fp16 globals
__device__ uint32_t g_Wf[40 * 64 * 32 * 2];                    // B frags (W), 640KB
__device__ uint32_t g_xf[(size_t)NG * TT * 8 * 2 * 32 * 4];    // A frags (x), 128MB
__device__ uint32_t g_hf[2][NG * 32 * 2 * 32 * 4];             // A frags (h), 2x512KB
__device__ unsigned g_flag[NG][NS][32];

// ---- prep: W -> B fragments.  B[k][n] = W[j=n][k] ----
__global__ void prep_w(const float* __restrict__ Wh, const float* __restrict__ Wx) {
    int i = blockIdx.x * blockDim.x + threadIdx.x;   // one b32 (2 fp16)
    if (i >= 40 * 64 * 32 * 2) return;
    int breg = i & 1;
    int lane = (i >> 1) & 31;
    int nt   = (i >> 6) & 63;
    int kt   = i >> 12;                  // 0..39 (0..31 = Wh, 32..39 = Wx)
    int j  = nt * 8 + (lane >> 2);
    int k2 = kt * 16 + 2 * (lane & 3) + 8 * breg;
    float v0, v1;
    if (kt < 32) { v0 = Wh[(size_t)j * HH + k2];        v1 = Wh[(size_t)j * HH + k2 + 1]; }
    else         { v0 = Wx[(size_t)j * DIN + (k2-512)]; v1 = Wx[(size_t)j * DIN + (k2-512) + 1]; }
    __half2 h = __floats2half2_rn(v0, v1);
    g_Wf[i] = *reinterpret_cast<uint32_t*>(&h);
}

// ---- prep: x -> A fragments (one-time) ----
__global__ void prep_x(const float* __restrict__ x) {
    size_t i = (size_t)blockIdx.x * blockDim.x + threadIdx.x;  // 8,388,608 lane-entries
    int lane = (int)(i & 31);
    int mt   = (int)((i >> 5) & 1);
    int kt   = (int)((i >> 6) & 7);
    int t    = (int)((i >> 9) & 1023);
    int g    = (int)(i >> 19);
    int r = mt * 16 + (lane >> 2);
    int k = kt * 16 + 2 * (lane & 3);
    uint32_t w[4];
    #pragma unroll
    for (int a = 0; a < 4; ++a) {
        int i_hi = a >> 1, i_r8 = a & 1;
        int b  = g * 32 + r + 8 * i_r8;
        int kk = k + 8 * i_hi;
        const float* p = &x[((size_t)b * TT + t) * DIN + kk];
        __half2 h = __floats2half2_rn(p[0], p[1]);
        w[a] = *reinterpret_cast<uint32_t*>(&h);
    }
    *reinterpret_cast<uint4*>(&g_xf[i * 4]) = make_uint4(w[0], w[1], w[2], w[3]);
}

__global__ void zero_kernel() {
    int i = blockIdx.x * blockDim.x + threadIdx.x;
    int stride = gridDim.x * blockDim.x;
    for (int k = i; k < NG * 32 * 2 * 32 * 4; k += stride) g_hf[0][k] = 0u;
    unsigned* f = &g_flag[0][0][0];
    for (int k = i; k < NG * NS * 32; k += stride) f[k] = 0u;
}

#define MMA(AC, A0, A1, A2, A3, B0, B1)                                        \
    asm volatile(                                                              \
        "mma.sync.aligned.m16n8k16.row.col.f32.f16.f16.f32 "                   \
        "{%0,%1,%2,%3}, {%4,%5,%6,%7}, {%8,%9}, {%0,%1,%2,%3};"                \
        : "+f"((AC)[0]), "+f"((AC)[1]), "+f"((AC)[2]), "+f"((AC)[3])           \
        : "r"(A0), "r"(A1), "r"(A2), "r"(A3), "r"(B0), "r"(B1))

#define LDS128(R0, R1, R2, R3, ADDR)                                           \
    asm volatile("ld.shared.v4.u32 {%0,%1,%2,%3}, [%4];"                       \
        : "=r"(R0), "=r"(R1), "=r"(R2), "=r"(R3) : "r"(ADDR))
#define LDS64(R0, R1, ADDR)                                                    \
    asm volatile("ld.shared.v2.u32 {%0,%1}, [%2];"                             \
        : "=r"(R0), "=r"(R1) : "r"(ADDR))

__global__ __launch_bounds__(NTHR, 1) void scan_kernel(
    const float* __restrict__ bx,
    const float* __restrict__ bh)
{
    extern __shared__ char smem[];
    const uint32_t sb = (uint32_t)__cvta_generic_to_shared(smem);
    float* bias_s = reinterpret_cast<float*>(smem + SM_BIAS);

    const int tid  = threadIdx.x;
    const int lane = tid & 31;
    const int wid  = tid >> 5;
    const int g    = blockIdx.x >> 3;
    const int s    = blockIdx.x & 7;
    const int mt_w = wid & 1;            // warp's m-tile (0/1)
    const int ng   = wid >> 1;           // warp's n-pair (0..3) -> nt {2ng, 2ng+1}

    // ---- load W fragments for this slice (once) ----
    {
        const uint4* src = reinterpret_cast<const uint4*>(g_Wf);
        uint4* dst = reinterpret_cast<uint4*>(smem + SM_W);
        for (int i = tid; i < 40 * 128; i += NTHR) {
            int kt = i >> 7, q = i & 127;
            dst[kt * 128 + q] = src[(size_t)(kt * 64 + s * 8) * 16 + q];
        }
    }
    if (tid < 64) bias_s[tid] = bx[s * 64 + tid] + bh[s * 64 + tid];

    uint4 pre0, pre1;
    // prologue: x fragments for t=0
    {
        const uint4* src = reinterpret_cast<const uint4*>(
            &g_xf[((size_t)g * TT + 0) * 2048]);
        pre0 = __ldg(src + tid * 2);
        pre1 = __ldg(src + tid * 2 + 1);
    }
    __syncthreads();

    #define LDG_H(PR, HC)                                                      \
        do {                                                                   \
            const uint4* src = reinterpret_cast<const uint4*>(                 \
                &g_hf[(PR)][(g * 32 + (HC) * 8) * 256]);                       \
            pre0 = __ldcg(src + tid * 2);                                      \
            pre1 = __ldcg(src + tid * 2 + 1);                                  \
        } while (0)

    #define LDG_X(TI)                                                          \
        do {                                                                   \
            const uint4* src = reinterpret_cast<const uint4*>(                 \
                &g_xf[((size_t)g * TT + (TI)) * 2048]);                        \
            pre0 = __ldg(src + tid * 2);                                       \
            pre1 = __ldg(src + tid * 2 + 1);                                   \
        } while (0)

    #define STS_A(BUF)                                                         \
        do {                                                                   \
            uint4* d = reinterpret_cast<uint4*>(smem + SM_A + (BUF) * 8192);   \
            d[tid * 2]     = pre0;                                             \
            d[tid * 2 + 1] = pre1;                                             \
        } while (0)

    #define COMPUTE(KB, BUF)                                                   \
        do {                                                                   \
            const uint32_t abase = sb + SM_A + (BUF) * 8192                    \
                                 + mt_w * 512 + lane * 16;                     \
            const uint32_t bbase = sb + SM_W + (KB) * 2048                     \
                                 + (2 * ng) * 256 + lane * 8;                  \
            _Pragma("unroll")                                                  \
            for (int kt = 0; kt < 8; ++kt) {                                   \
                uint32_t a0, a1, a2, a3, b0, b1, b2, b3;                       \
                LDS128(a0, a1, a2, a3, abase + kt * 1024);                     \
                LDS64(b0, b1, bbase + kt * 2048);                              \
                LDS64(b2, b3, bbase + kt * 2048 + 256);                        \
                MMA(acc0, a0, a1, a2, a3, b0, b1);                             \
                MMA(acc1, a0, a1, a2, a3, b2, b3);                             \
            }                                                                  \
        } while (0)

    for (int t = 0; t < TT; ++t) {
        const int pr = t & 1, pw = pr ^ 1;
        float acc0[4] = {0.f, 0.f, 0.f, 0.f};
        float acc1[4] = {0.f, 0.f, 0.f, 0.f};

        // q0: x chunk (B kt 32..39)
        STS_A(0);
        __syncthreads();
        LDG_H(pr, 0);
        COMPUTE(32, 0);
        // q1..q3: h chunks 0..2
        STS_A(1);
        __syncthreads();
        LDG_H(pr, 1);
        COMPUTE(0, 1);

        STS_A(0);
        __syncthreads();
        LDG_H(pr, 2);
        COMPUTE(8, 0);

        STS_A(1);
        __syncthreads();
        LDG_H(pr, 3);
        COMPUTE(16, 1);
        // q4: h chunk 3; prefetch x(t+1)
        STS_A(0);
        __syncthreads();
        {
            const int tn = (t + 1 < TT) ? t + 1 : TT - 1;
            LDG_X(tn);
        }
        COMPUTE(24, 0);

        // ---- epilogue: bias + tanh, pack fp16x2, publish in fragment layout ----
        {
            uint32_t* hdst = &g_hf[pw][0];
            #pragma unroll
            for (int tile = 0; tile < 2; ++tile) {
                const float* ac = tile ? acc1 : acc0;
                const int ntl = 2 * ng + tile;
                const int jl  = ntl * 8 + 2 * (lane & 3);
                const float bf0 = bias_s[jl], bf1 = bias_s[jl + 1];
                const int kt = s * 4 + (ntl >> 1);
                #pragma unroll
                for (int ir = 0; ir < 2; ++ir) {
                    float h0 = tanhf(ac[2 * ir + 0] + bf0);
                    float h1 = tanhf(ac[2 * ir + 1] + bf1);
                    __half2 hh = __floats2half2_rn(h0, h1);
                    int a = 2 * (ntl & 1) + ir;
                    __stcg(&hdst[((g * 32 + kt) * 2 + mt_w) * 128 + lane * 4 + a],
                           *reinterpret_cast<uint32_t*>(&hh));
                }
            }
        }

        // ---- R8-proven cross-CTA step barrier ----
        __syncthreads();
        if (tid == 0) {
            asm volatile("fence.acq_rel.gpu;" ::: "memory");
            asm volatile("st.release.gpu.global.u32 [%0], %1;"
                         :: "l"(&g_flag[g][s][0]), "r"((unsigned)(t + 1))
                         : "memory");
        }
        if (tid < NS) {
            const unsigned tgt = (unsigned)(t + 1);
            unsigned v;
            do {
                asm volatile("ld.acquire.gpu.global.u32 %0, [%1];"
                             : "=r"(v) : "l"(&g_flag[g][tid][0]));
            } while (v < tgt);
        }
        __syncthreads();
    }
    #undef LDG_H
    #undef LDG_X
    #undef STS_A
    #undef COMPUTE
}

// y[b][o] = by[o] + sum_k h_T[b][k] * Wy[o][k] ; h_T fragments in g_hf[0]
__global__ __launch_bounds__(128, 1) void y_kernel(
    const float* __restrict__ Wy,
    const float* __restrict__ by,
    float* __restrict__ y)
{
    __shared__ float hs[HH];
    const int b = blockIdx.x, o = threadIdx.x;
    const int g = b >> 5, m = b & 31, mt = m >> 4;
    const uint32_t* hf = &g_hf[0][0];
    #pragma unroll
    for (int w = 0; w < 2; ++w) {
        int k  = o * 4 + w * 2;
        int kt = k >> 4, kl = k & 15;
        int lane = ((m & 7) << 2) | ((kl & 7) >> 1);
        int a = 2 * (kl >> 3) + ((m >> 3) & 1);
        uint32_t word = hf[((g * 32 + kt) * 2 + mt) * 128 + lane * 4 + a];
        __half2 hh = *reinterpret_cast<__half2*>(&word);
        hs[k]     = __low2float(hh);
        hs[k + 1] = __high2float(hh);
    }
    __syncthreads();
    const float4* w4 = reinterpret_cast<const float4*>(&Wy[(size_t)o * HH]);
    float acc = by[o];
    #pragma unroll 8
    for (int q = 0; q < HH / 4; ++q) {
        float4 w = __ldg(&w4[q]);
        acc = fmaf(w.x, hs[4 * q + 0], acc);
        acc = fmaf(w.y, hs[4 * q + 1], acc);
        acc = fmaf(w.z, hs[4 * q + 2], acc);
        acc = fmaf(w.w, hs[4 * q + 3], acc);
    }
    y[(size_t)b * DOUT + o] = acc;
}

extern "C" void kernel_launch(void* const* d_in, const int* in_sizes, int n_in,
                              void* d_out, int out_size) {
    const float* x  = (const float*)d_in[0];
    const float* Wx = (const float*)d_in[1];
    const float* bx = (const float*)d_in[2];
    const float* Wh = (const float*)d_in[3];
    const float* bh = (const float*)d_in[4];
    const float* Wy = (const float*)d_in[5];
    const float* by = (const float*)d_in[6];
    float* y = (float*)d_out;

    cudaFuncSetAttribute(scan_kernel,
                         cudaFuncAttributeMaxDynamicSharedMemorySize, SMEM_TOTAL);

    prep_w<<<640, 256>>>(Wh, Wx);
    prep_x<<<32768, 256>>>(x);
    zero_kernel<<<128, 256>>>();
    scan_kernel<<<NG * NS, NTHR, SMEM_TOTAL>>>(bx, bh);
    y_kernel<<<512, 128>>>(Wy, by, y);
}

// round 14
// speedup vs baseline: 4.3374x; 1.1433x over previous
#include <cuda_runtime.h>
#include <cuda_fp16.h>
#include <math.h>
#include <stdint.h>

#define TT   1024
#define DIN  128
#define HH   512
#define DOUT 128
#define NG   16
#define NS   8
#define NTHR 256

// smem byte offsets
#define SM_W   0                        // [40 kt][4 ng][32 lane][16B] = 81920 B
#define SM_A   81920                    // [32 kt][2 mt][32 lane][16B] = 32768 B
#define SM_BIAS (SM_A + 32768)          // 64 floats
#define SMEM_TOTAL (SM_BIAS + 256)

// fragment-order fp16 globals
__device__ uint32_t g_Wf[40 * 64 * 32 * 2];                    // B frags (W), 640KB
__device__ uint32_t g_xf[(size_t)NG * TT * 8 * 2 * 32 * 4];    // A frags (x), 128MB
__device__ uint32_t g_hf[2][NG * 32 * 2 * 32 * 4];             // A frags (h), 2x512KB
__device__ unsigned g_flag[NG][NS][32];

// ---- prep: W -> B fragments.  B[k][n] = W[j=n][k] ----
__global__ void prep_w(const float* __restrict__ Wh, const float* __restrict__ Wx) {
    int i = blockIdx.x * blockDim.x + threadIdx.x;   // one b32 (2 fp16)
    if (i >= 40 * 64 * 32 * 2) return;
    int breg = i & 1;
    int lane = (i >> 1) & 31;
    int nt   = (i >> 6) & 63;
    int kt   = i >> 12;                  // 0..39 (0..31 = Wh, 32..39 = Wx)
    int j  = nt * 8 + (lane >> 2);
    int k2 = kt * 16 + 2 * (lane & 3) + 8 * breg;
    float v0, v1;
    if (kt < 32) { v0 = Wh[(size_t)j * HH + k2];        v1 = Wh[(size_t)j * HH + k2 + 1]; }
    else         { v0 = Wx[(size_t)j * DIN + (k2-512)]; v1 = Wx[(size_t)j * DIN + (k2-512) + 1]; }
    __half2 h = __floats2half2_rn(v0, v1);
    g_Wf[i] = *reinterpret_cast<uint32_t*>(&h);
}

// ---- prep: x -> A fragments (one-time) ----
__global__ void prep_x(const float* __restrict__ x) {
    size_t i = (size_t)blockIdx.x * blockDim.x + threadIdx.x;  // 8,388,608 lane-entries
    int lane = (int)(i & 31);
    int mt   = (int)((i >> 5) & 1);
    int kt   = (int)((i >> 6) & 7);
    int t    = (int)((i >> 9) & 1023);
    int g    = (int)(i >> 19);
    int r = mt * 16 + (lane >> 2);
    int k = kt * 16 + 2 * (lane & 3);
    uint32_t w[4];
    #pragma unroll
    for (int a = 0; a < 4; ++a) {
        int i_hi = a >> 1, i_r8 = a & 1;
        int b  = g * 32 + r + 8 * i_r8;
        int kk = k + 8 * i_hi;
        const float* p = &x[((size_t)b * TT + t) * DIN + kk];
        __half2 h = __floats2half2_rn(p[0], p[1]);
        w[a] = *reinterpret_cast<uint32_t*>(&h);
    }
    *reinterpret_cast<uint4*>(&g_xf[i * 4]) = make_uint4(w[0], w[1], w[2], w[3]);
}

__global__ void zero_kernel() {
    int i = blockIdx.x * blockDim.x + threadIdx.x;
    int stride = gridDim.x * blockDim.x;
    for (int k = i; k < NG * 32 * 2 * 32 * 4; k += stride) g_hf[0][k] = 0u;
    unsigned* f = &g_flag[0][0][0];
    for (int k = i; k < NG * NS * 32; k += stride) f[k] = 0u;
}

#define MMA(AC, A0, A1, A2, A3, B0, B1)                                        \
    asm volatile(                                                              \
        "mma.sync.aligned.m16n8k16.row.col.f32.f16.f16.f32 "                   \
        "{%0,%1,%2,%3}, {%4,%5,%6,%7}, {%8,%9}, {%0,%1,%2,%3};"                \
        : "+f"((AC)[0]), "+f"((AC)[1]), "+f"((AC)[2]), "+f"((AC)[3])           \
        : "r"(A0), "r"(A1), "r"(A2), "r"(A3), "r"(B0), "r"(B1))

#define LDS128(R0, R1, R2, R3, ADDR)                                           \
    asm volatile("ld.shared.v4.u32 {%0,%1,%2,%3}, [%4];"                       \
        : "=r"(R0), "=r"(R1), "=r"(R2), "=r"(R3) : "r"(ADDR))

__global__ __launch_bounds__(NTHR, 1) void scan_kernel(
    const float* __restrict__ bx,
    const float* __restrict__ bh)
{
    extern __shared__ char smem[];
    const uint32_t sb = (uint32_t)__cvta_generic_to_shared(smem);
    float* bias_s = reinterpret_cast<float*>(smem + SM_BIAS);

    const int tid  = threadIdx.x;
    const int lane = tid & 31;
    const int wid  = tid >> 5;
    const int g    = blockIdx.x >> 3;
    const int s    = blockIdx.x & 7;
    const int mt_w = wid & 1;            // warp's m-tile (0/1)
    const int ng   = wid >> 1;           // warp's n-pair (0..3) -> nt {2ng, 2ng+1}

    // ---- load W fragments, repacked ng-paired: [kt][ng][lane][b0,b1,b2,b3] ----
    {
        const uint2* src = reinterpret_cast<const uint2*>(g_Wf);
        uint4* dst = reinterpret_cast<uint4*>(smem + SM_W);
        for (int i = tid; i < 40 * 4 * 32; i += NTHR) {
            int ln = i & 31, gg = (i >> 5) & 3, kt = i >> 7;
            uint2 a = src[(size_t)(kt * 64 + s * 8 + 2 * gg) * 32 + ln];
            uint2 b = src[(size_t)(kt * 64 + s * 8 + 2 * gg + 1) * 32 + ln];
            dst[i] = make_uint4(a.x, a.y, b.x, b.y);
        }
    }
    if (tid < 64) bias_s[tid] = bx[s * 64 + tid] + bh[s * 64 + tid];
    __syncthreads();

    // x fragments in registers: warp's mt, kt 0..7
    uint4 xr[8];
    #pragma unroll
    for (int kt = 0; kt < 8; ++kt)
        xr[kt] = __ldg(reinterpret_cast<const uint4*>(g_xf) +
                       (size_t)((((g * TT + 0) * 8 + kt) * 2 + mt_w) * 32 + lane));

    const uint32_t abase = sb + SM_A + mt_w * 512 + lane * 16;
    const uint32_t bbase = sb + SM_W + ng * 512 + lane * 16;

    for (int t = 0; t < TT; ++t) {
        const int pr = t & 1, pw = pr ^ 1;
        float acc0[4] = {0.f, 0.f, 0.f, 0.f};
        float acc1[4] = {0.f, 0.f, 0.f, 0.f};

        // ---- x MMAs from registers (B kt 32..39) — before the peer wait ----
        #pragma unroll
        for (int kt = 0; kt < 8; ++kt) {
            uint32_t b0, b1, b2, b3;
            LDS128(b0, b1, b2, b3, bbase + (32 + kt) * 2048);
            MMA(acc0, xr[kt].x, xr[kt].y, xr[kt].z, xr[kt].w, b0, b1);
            MMA(acc1, xr[kt].x, xr[kt].y, xr[kt].z, xr[kt].w, b2, b3);
        }
        // prefetch x(t+1) into regs (in flight through rest of step)
        {
            const int tn = (t + 1 < TT) ? t + 1 : TT - 1;
            #pragma unroll
            for (int kt = 0; kt < 8; ++kt)
                xr[kt] = __ldg(reinterpret_cast<const uint4*>(g_xf) +
                               (size_t)((((g * TT + tn) * 8 + kt) * 2 + mt_w) * 32 + lane));
        }

        // ---- wait peers: h_t published ----
        if (tid < NS) {
            unsigned v;
            do {
                asm volatile("ld.acquire.gpu.global.u32 %0, [%1];"
                             : "=r"(v) : "l"(&g_flag[g][tid][0]));
            } while (v < (unsigned)t);
        }
        __syncthreads();

        // ---- single-shot h stage: 32 KB, MLP 8 ----
        {
            uint4 pre[8];
            const uint4* src = reinterpret_cast<const uint4*>(&g_hf[pr][0]);
            #pragma unroll
            for (int hc = 0; hc < 4; ++hc) {
                pre[2 * hc]     = __ldcg(src + (size_t)(g * 32 + hc * 8) * 64 + tid * 2);
                pre[2 * hc + 1] = __ldcg(src + (size_t)(g * 32 + hc * 8) * 64 + tid * 2 + 1);
            }
            #pragma unroll
            for (int hc = 0; hc < 4; ++hc) {
                uint4* d = reinterpret_cast<uint4*>(smem + SM_A + hc * 8192);
                d[tid * 2]     = pre[2 * hc];
                d[tid * 2 + 1] = pre[2 * hc + 1];
            }
        }
        __syncthreads();

        // ---- h MMAs: 32 kt, 2 LDS.128 + 2 MMA each ----
        #pragma unroll
        for (int kt = 0; kt < 32; ++kt) {
            uint32_t a0, a1, a2, a3, b0, b1, b2, b3;
            LDS128(a0, a1, a2, a3, abase + kt * 1024);
            LDS128(b0, b1, b2, b3, bbase + kt * 2048);
            MMA(acc0, a0, a1, a2, a3, b0, b1);
            MMA(acc1, a0, a1, a2, a3, b2, b3);
        }

        // ---- epilogue: bias + tanh, pack fp16x2, publish in fragment layout ----
        {
            uint32_t* hdst = &g_hf[pw][0];
            #pragma unroll
            for (int tile = 0; tile < 2; ++tile) {
                const float* ac = tile ? acc1 : acc0;
                const int ntl = 2 * ng + tile;
                const int jl  = ntl * 8 + 2 * (lane & 3);
                const float bf0 = bias_s[jl], bf1 = bias_s[jl + 1];
                const int kt = s * 4 + (ntl >> 1);
                #pragma unroll
                for (int ir = 0; ir < 2; ++ir) {
                    float h0 = tanhf(ac[2 * ir + 0] + bf0);
                    float h1 = tanhf(ac[2 * ir + 1] + bf1);
                    __half2 hh = __floats2half2_rn(h0, h1);
                    int a = 2 * (ntl & 1) + ir;
                    __stcg(&hdst[((g * 32 + kt) * 2 + mt_w) * 128 + lane * 4 + a],
                           *reinterpret_cast<uint32_t*>(&hh));
                }
            }
        }

        // ---- cross-CTA step barrier (R8-proven) ----
        __syncthreads();
        if (tid == 0) {
            asm volatile("fence.acq_rel.gpu;" ::: "memory");
            asm volatile("st.release.gpu.global.u32 [%0], %1;"
                         :: "l"(&g_flag[g][s][0]), "r"((unsigned)(t + 1))
                         : "memory");
        }
    }
}

// y[b][o] = by[o] + sum_k h_T[b][k] * Wy[o][k] ; h_T fragments in g_hf[0]
__global__ __launch_bounds__(128, 1) void y_kernel(
    const float* __restrict__ Wy,
    const float* __restrict__ by,
    float* __restrict__ y)
{
    __shared__ float hs[HH];
    const int b = blockIdx.x, o = threadIdx.x;
    const int g = b >> 5, m = b & 31, mt = m >> 4;
    const uint32_t* hf = &g_hf[0][0];
    #pragma unroll
    for (int w = 0; w < 2; ++w) {
        int k  = o * 4 + w * 2;
        int kt = k >> 4, kl = k & 15;
        int lane = ((m & 7) << 2) | ((kl & 7) >> 1);
        int a = 2 * (kl >> 3) + ((m >> 3) & 1);
        uint32_t word = hf[((g * 32 + kt) * 2 + mt) * 128 + lane * 4 + a];
        __half2 hh = *reinterpret_cast<__half2*>(&word);
        hs[k]     = __low2float(hh);
        hs[k + 1] = __high2float(hh);
    }
    __syncthreads();
    const float4* w4 = reinterpret_cast<const float4*>(&Wy[(size_t)o * HH]);
    float acc = by[o];
    #pragma unroll 8
    for (int q = 0; q < HH / 4; ++q) {
        float4 w = __ldg(&w4[q]);
        acc = fmaf(w.x, hs[4 * q + 0], acc);
        acc = fmaf(w.y, hs[4 * q + 1], acc);
        acc = fmaf(w.z, hs[4 * q + 2], acc);
        acc = fmaf(w.w, hs[4 * q + 3], acc);
    }
    y[(size_t)b * DOUT + o] = acc;
}

extern "C" void kernel_launch(void* const* d_in, const int* in_sizes, int n_in,
                              void* d_out, int out_size) {
    const float* x  = (const float*)d_in[0];
    const float* Wx = (const float*)d_in[1];
    const float* bx = (const float*)d_in[2];
    const float* Wh = (const float*)d_in[3];
    const float* bh = (const float*)d_in[4];
    const float* Wy = (const float*)d_in[5];
    const float* by = (const float*)d_in[6];
    float* y = (float*)d_out;

    cudaFuncSetAttribute(scan_kernel,
                         cudaFuncAttributeMaxDynamicSharedMemorySize, SMEM_TOTAL);

    prep_w<<<640, 256>>>(Wh, Wx);
    prep_x<<<32768, 256>>>(x);
    zero_kernel<<<128, 256>>>();
    scan_kernel<<<NG * NS, NTHR, SMEM_TOTAL>>>(bx, bh);
    y_kernel<<<512, 128>>>(Wy, by, y);
}